// round 7
// baseline (speedup 1.0000x reference)
#include <cuda_runtime.h>
#include <cuda_bf16.h>
#include <math.h>

#define Bsz 64
#define Hs  512
#define Ss  256
#define Vv  32000

// ------------------- scratch (__device__ globals, no allocation) -------------
__device__ float g_edt[Bsz * Ss];            // encdot [b'][s']
__device__ float g_norm[Ss * Bsz];           // normalized [s][b]
__device__ float g_aspart[4 * Bsz * 1024];   // attn_sum split-S partials [sp][b][d]
__device__ float g_gpart[4 * Bsz * 2048];    // split-K partial gates
__device__ float g_xcat[Bsz * 2048];         // fp32 [.. | input(1024:1536) | h0[0](1536:2048)]
__device__ float g_x1[Bsz * 1024];           // fp32 [h1(0:512) | h0[1](512:1024)]
__device__ float g_h2f[Bsz * 512];           // fp32 h2

__device__ __forceinline__ void bfsplit(float x, __nv_bfloat16& h, __nv_bfloat16& l) {
    h = __float2bfloat16(x);
    l = __float2bfloat16(x - __bfloat162float(h));
}

// ------------------- attention: encdot[s',b'] = enc[s',b',:] . We ------------
__global__ void k_encdot(const float* __restrict__ enc,
                         const float* __restrict__ attn_W) {
    __shared__ __align__(16) float We[1024];
    for (int i = threadIdx.x; i < 1024; i += blockDim.x) We[i] = attn_W[512 + i];
    __syncthreads();
    int wid  = (blockIdx.x * blockDim.x + threadIdx.x) >> 5;
    int lane = threadIdx.x & 31;
    const float4* e4 = (const float4*)(enc + (size_t)wid * 1024);
    const float4* w4 = (const float4*)We;
    float acc = 0.f;
#pragma unroll
    for (int it = 0; it < 8; it++) {
        float4 a = e4[it * 32 + lane];
        float4 w = w4[it * 32 + lane];
        acc += a.x * w.x + a.y * w.y + a.z * w.z + a.w * w.w;
    }
#pragma unroll
    for (int o = 16; o; o >>= 1) acc += __shfl_xor_sync(0xFFFFFFFFu, acc, o);
    if (lane == 0) {
        int sp = wid >> 6, bp = wid & 63;
        g_edt[bp * 256 + sp] = acc;
    }
}

// ------------------- fused softmax + pack (fp32) -----------------------------
__global__ void k_softpack(const float* __restrict__ input,
                           const float* __restrict__ h0) {
    if (blockIdx.x < 32) {
        int s    = (blockIdx.x * blockDim.x + threadIdx.x) >> 5;
        int lane = threadIdx.x & 31;
        int base = (s >> 2) * 256 + (s & 3) * 64;
        float v0 = g_edt[base + lane];
        float v1 = g_edt[base + 32 + lane];
        float m = fmaxf(v0, v1);
#pragma unroll
        for (int o = 16; o; o >>= 1) m = fmaxf(m, __shfl_xor_sync(0xFFFFFFFFu, m, o));
        float e0 = expf(v0 - m), e1 = expf(v1 - m);
        float sum = e0 + e1;
#pragma unroll
        for (int o = 16; o; o >>= 1) sum += __shfl_xor_sync(0xFFFFFFFFu, sum, o);
        float inv = 1.f / sum;
        g_norm[s * 64 + lane]      = e0 * inv;
        g_norm[s * 64 + 32 + lane] = e1 * inv;
    } else {
        int i = (blockIdx.x - 32) * blockDim.x + threadIdx.x;   // 0..32767
        int b = i >> 9, j = i & 511;
        g_xcat[b * 2048 + 1024 + j] = input[i];
        g_xcat[b * 2048 + 1536 + j] = h0[i];            // h0[0]
        g_x1[b * 1024 + 512 + j]    = h0[32768 + i];    // h0[1]
    }
}

// ------------------- attn_sum split-S partials -------------------------------
__global__ void k_attnsum(const float* __restrict__ enc) {
    int b     = blockIdx.x;        // 0..63
    int chunk = blockIdx.y;        // 0..3
    int sp    = blockIdx.z;        // 0..3 (S split)
    __shared__ float nc[64];
    if (threadIdx.x < 64)
        nc[threadIdx.x] = g_norm[(sp * 64 + threadIdx.x) * 64 + b];
    __syncthreads();
    int d = chunk * 256 + threadIdx.x;
    const float* ep = enc + (size_t)sp * 64 * 65536 + b * 1024 + d;
    float a0 = 0.f, a1 = 0.f, a2 = 0.f, a3 = 0.f;
#pragma unroll 4
    for (int s = 0; s < 64; s += 4) {
        a0 += nc[s]     * ep[(s)     * 65536];
        a1 += nc[s + 1] * ep[(s + 1) * 65536];
        a2 += nc[s + 2] * ep[(s + 2) * 65536];
        a3 += nc[s + 3] * ep[(s + 3) * 65536];
    }
    g_aspart[(sp * 64 + b) * 1024 + d] = (a0 + a1) + (a2 + a3);
}

// ------------------- tensor-core GEMM: out = A(64,K) @ [WA|WB]^T + bias ------
// A is fp32; hi/lo bf16 split happens in the smem-store stage. For k < partK,
// A is the sum of 4 split-S partials (row stride 1024). Double-buffered smem,
// one __syncthreads per 32-K iter. 256 thr, tile 64x64, warps 2(M)x4(N).
__device__ __forceinline__ void ldmx4(unsigned* r, unsigned addr) {
    asm volatile("ldmatrix.sync.aligned.m8n8.x4.shared.b16 {%0,%1,%2,%3}, [%4];"
                 : "=r"(r[0]), "=r"(r[1]), "=r"(r[2]), "=r"(r[3]) : "r"(addr));
}
__device__ __forceinline__ void mma16816(float* d, const unsigned* a, const unsigned* b) {
    asm volatile("mma.sync.aligned.m16n8k16.row.col.f32.bf16.bf16.f32 "
                 "{%0,%1,%2,%3},{%4,%5,%6,%7},{%8,%9},{%0,%1,%2,%3};"
                 : "+f"(d[0]), "+f"(d[1]), "+f"(d[2]), "+f"(d[3])
                 : "r"(a[0]), "r"(a[1]), "r"(a[2]), "r"(a[3]), "r"(b[0]), "r"(b[1]));
}
__device__ __forceinline__ uint4 pack8(float4 v0, float4 v1, bool lo) {
    __nv_bfloat16 h, l;
    __nv_bfloat162 p[4];
    float f[8] = {v0.x, v0.y, v0.z, v0.w, v1.x, v1.y, v1.z, v1.w};
#pragma unroll
    for (int i = 0; i < 4; i++) {
        __nv_bfloat16 a, b;
        bfsplit(f[2 * i], h, l);     a = lo ? l : h;
        bfsplit(f[2 * i + 1], h, l); b = lo ? l : h;
        p[i].x = a; p[i].y = b;
    }
    uint4 r;
    r.x = *(unsigned*)&p[0]; r.y = *(unsigned*)&p[1];
    r.z = *(unsigned*)&p[2]; r.w = *(unsigned*)&p[3];
    return r;
}

__global__ void __launch_bounds__(256) tc_gemm(
    const float* __restrict__ A, int K,
    const float* __restrict__ Apart, int partK,
    const float* __restrict__ WA, int KA, const float* __restrict__ WB,
    const float* __restrict__ bias0, const float* __restrict__ bias1,
    float* __restrict__ out, int N, int kChunk)
{
    __shared__ __align__(16) __nv_bfloat16 sAh[2][64 * 40], sAl[2][64 * 40];
    __shared__ __align__(16) __nv_bfloat16 sBh[2][64 * 40], sBl[2][64 * 40];
    int tid = threadIdx.x, warp = tid >> 5, lane = tid & 31;
    int warp_m = warp >> 2, warp_n = warp & 3;
    int j0   = blockIdx.x * 64;
    int kidx = blockIdx.y;
    int kbeg = kidx * kChunk, kend = kbeg + kChunk;
    int KB = K - KA;
    float acc[2][2][4] = {};

    // ldmatrix lane->address components (identical mapping to validated R3/R6)
    int a_row = lane & 15;
    int a_k   = (lane >> 4) * 8;
    int b_row = warp_n * 16 + ((lane >> 4) << 3) + (lane & 7);
    int b_k   = ((lane >> 3) & 1) * 8;

    unsigned sAh_b = (unsigned)__cvta_generic_to_shared(&sAh[0][0]);
    unsigned sAl_b = (unsigned)__cvta_generic_to_shared(&sAl[0][0]);
    unsigned sBh_b = (unsigned)__cvta_generic_to_shared(&sBh[0][0]);
    unsigned sBl_b = (unsigned)__cvta_generic_to_shared(&sBl[0][0]);
    const unsigned STG = 64 * 40 * 2;   // 5120 bytes per stage

    // load-index precompute
    int arow = tid >> 2, ac8 = tid & 3;            // A: 64 rows x 4 groups of 8 cols
    int wrow = tid >> 3, wc4 = tid & 7;            // W: 32 rows x 8 float4 (x2 halves)

    // staging registers
    float4 rA0, rA1, rW0, rW1, rW2, rW3;

    auto loadregs = [&](int k0) {
        if (k0 < partK) {
            const float* p0 = Apart + (size_t)arow * 1024 + k0 + ac8 * 8;
            rA0 = *(const float4*)p0;
            rA1 = *(const float4*)(p0 + 4);
#pragma unroll
            for (int p = 1; p < 4; p++) {
                float4 u0 = *(const float4*)(p0 + p * 65536);
                float4 u1 = *(const float4*)(p0 + p * 65536 + 4);
                rA0.x += u0.x; rA0.y += u0.y; rA0.z += u0.z; rA0.w += u0.w;
                rA1.x += u1.x; rA1.y += u1.y; rA1.z += u1.z; rA1.w += u1.w;
            }
        } else {
            const float* pa = A + (size_t)arow * K + k0 + ac8 * 8;
            rA0 = *(const float4*)pa;
            rA1 = *(const float4*)(pa + 4);
        }
        const float* wp; int ld, kc;
        if (k0 < KA) { wp = WA; ld = KA; kc = k0; }
        else         { wp = WB; ld = KB; kc = k0 - KA; }
        rW0 = *(const float4*)(wp + (size_t)(j0 + wrow) * ld + kc + wc4 * 4);
        rW1 = *(const float4*)(wp + (size_t)(j0 + wrow) * ld + kc + wc4 * 4 + 4 * 0 + 0);
        rW1 = *(const float4*)(wp + (size_t)(j0 + wrow + 32) * ld + kc + wc4 * 4);
        rW2 = rW1;  // (kept simple: rW1 holds second half row)
        (void)rW3;
    };
    auto storeregs = [&](int st) {
        *(uint4*)((char*)sAh[st] + arow * 80 + ac8 * 16) = pack8(rA0, rA1, false);
        *(uint4*)((char*)sAl[st] + arow * 80 + ac8 * 16) = pack8(rA0, rA1, true);
        // W: each thread owns 4 cols of rows wrow and wrow+32
#pragma unroll
        for (int half = 0; half < 2; half++) {
            float4 v = half ? rW1 : rW0;
            int row = wrow + half * 32;
            __nv_bfloat16 hx, lx, hy, ly, hz, lz, hw, lw;
            bfsplit(v.x, hx, lx); bfsplit(v.y, hy, ly);
            bfsplit(v.z, hz, lz); bfsplit(v.w, hw, lw);
            __nv_bfloat162 H0; H0.x = hx; H0.y = hy;
            __nv_bfloat162 H1; H1.x = hz; H1.y = hw;
            __nv_bfloat162 L0; L0.x = lx; L0.y = ly;
            __nv_bfloat162 L1; L1.x = lz; L1.y = lw;
            char* bh = (char*)sBh[st] + row * 80 + wc4 * 8;
            char* bl = (char*)sBl[st] + row * 80 + wc4 * 8;
            *(__nv_bfloat162*)bh = H0; *(__nv_bfloat162*)(bh + 4) = H1;
            *(__nv_bfloat162*)bl = L0; *(__nv_bfloat162*)(bl + 4) = L1;
        }
    };

    int nIter = (kend - kbeg) >> 5;
    loadregs(kbeg);
    storeregs(0);
    __syncthreads();
    int stage = 0;
    for (int it = 0; it < nIter; it++) {
        bool has_next = (it + 1 < nIter);
        if (has_next) loadregs(kbeg + (it + 1) * 32);
        unsigned sb = stage * STG;
#pragma unroll
        for (int kk = 0; kk < 32; kk += 16) {
            unsigned bh[4], bl[4];
            unsigned baddr = (unsigned)(b_row * 80 + (kk + b_k) * 2) + sb;
            ldmx4(bh, sBh_b + baddr);
            ldmx4(bl, sBl_b + baddr);
#pragma unroll
            for (int mi = 0; mi < 2; mi++) {
                unsigned ah[4], al[4];
                int grow = warp_m * 32 + mi * 16 + a_row;
                unsigned aaddr = (unsigned)(grow * 80 + (kk + a_k) * 2) + sb;
                ldmx4(ah, sAh_b + aaddr);
                ldmx4(al, sAl_b + aaddr);
                mma16816(acc[mi][0], ah, &bh[0]);
                mma16816(acc[mi][0], ah, &bl[0]);
                mma16816(acc[mi][0], al, &bh[0]);
                mma16816(acc[mi][1], ah, &bh[2]);
                mma16816(acc[mi][1], ah, &bl[2]);
                mma16816(acc[mi][1], al, &bh[2]);
            }
        }
        if (has_next) storeregs(stage ^ 1);
        __syncthreads();
        stage ^= 1;
    }

    int orow = lane >> 2;
    int ocol = (lane & 3) * 2;
    float* op = out + (size_t)kidx * 64 * N;
#pragma unroll
    for (int mi = 0; mi < 2; mi++) {
#pragma unroll
        for (int nj = 0; nj < 2; nj++) {
            int col = j0 + warp_n * 16 + nj * 8 + ocol;
            float bA = 0.f, bB = 0.f;
            if (kidx == 0) {
                if (bias0) { bA += bias0[col]; bB += bias0[col + 1]; }
                if (bias1) { bA += bias1[col]; bB += bias1[col + 1]; }
            }
            int r0 = warp_m * 32 + mi * 16 + orow;
            op[(size_t)r0 * N + col]           = acc[mi][nj][0] + bA;
            op[(size_t)r0 * N + col + 1]       = acc[mi][nj][1] + bB;
            op[(size_t)(r0 + 8) * N + col]     = acc[mi][nj][2] + bA;
            op[(size_t)(r0 + 8) * N + col + 1] = acc[mi][nj][3] + bB;
        }
    }
}

// ------------------- LSTM cell epilogues (sum split-K parts) -----------------
__device__ __forceinline__ float sigf(float x) { return 1.f / (1.f + expf(-x)); }

__global__ void k_cell0(const float* __restrict__ c0,
                        float* __restrict__ h_out,
                        float* __restrict__ c_out) {
    int idx = blockIdx.x * blockDim.x + threadIdx.x;
    int b = idx >> 9, j = idx & 511;
    int base = b * 2048;
    float gi = 0, gf = 0, gg = 0, go = 0;
#pragma unroll
    for (int p = 0; p < 4; p++) {
        const float* gp = g_gpart + p * 64 * 2048 + base;
        gi += gp[j]; gf += gp[512 + j]; gg += gp[1024 + j]; go += gp[1536 + j];
    }
    float c = sigf(gf) * c0[idx] + sigf(gi) * tanhf(gg);
    float h = sigf(go) * tanhf(c);
    h_out[idx] = h;
    c_out[idx] = c;
    g_x1[b * 1024 + j] = h;
}

__global__ void k_cell1(const float* __restrict__ c0b,
                        float* __restrict__ out0,
                        float* __restrict__ h_out,
                        float* __restrict__ c_out) {
    int idx = blockIdx.x * blockDim.x + threadIdx.x;
    int b = idx >> 9, j = idx & 511;
    int base = b * 2048;
    float gi = 0, gf = 0, gg = 0, go = 0;
#pragma unroll
    for (int p = 0; p < 4; p++) {
        const float* gp = g_gpart + p * 64 * 2048 + base;
        gi += gp[j]; gf += gp[512 + j]; gg += gp[1024 + j]; go += gp[1536 + j];
    }
    float c = sigf(gf) * c0b[idx] + sigf(gi) * tanhf(gg);
    float h = sigf(go) * tanhf(c);
    out0[idx]  = h;
    h_out[idx] = h;
    c_out[idx] = c;
    g_h2f[idx] = h;
}

// ------------------- launch ---------------------------------------------------
extern "C" void kernel_launch(void* const* d_in, const int* in_sizes, int n_in,
                              void* d_out, int out_size) {
    const float* input = (const float*)d_in[0];
    const float* h0    = (const float*)d_in[1];
    const float* c0    = (const float*)d_in[2];
    const float* enc   = (const float*)d_in[3];
    const float* attnW = (const float*)d_in[4];
    const float* w_ih0 = (const float*)d_in[6];
    const float* w_hh0 = (const float*)d_in[7];
    const float* b_ih0 = (const float*)d_in[8];
    const float* b_hh0 = (const float*)d_in[9];
    const float* w_ih1 = (const float*)d_in[10];
    const float* w_hh1 = (const float*)d_in[11];
    const float* b_ih1 = (const float*)d_in[12];
    const float* b_hh1 = (const float*)d_in[13];
    const float* out_W = (const float*)d_in[14];
    const float* out_b = (const float*)d_in[15];
    float* out = (float*)d_out;

    float *p_gpart, *p_xcat, *p_x1, *p_h2f, *p_aspart;
    cudaGetSymbolAddress((void**)&p_gpart,  g_gpart);
    cudaGetSymbolAddress((void**)&p_xcat,   g_xcat);
    cudaGetSymbolAddress((void**)&p_x1,     g_x1);
    cudaGetSymbolAddress((void**)&p_h2f,    g_h2f);
    cudaGetSymbolAddress((void**)&p_aspart, g_aspart);

    // Output layout: [output | h_new | c_new | pred]
    float* o_output = out;
    float* o_h1 = out + 32768;
    float* o_h2 = out + 65536;
    float* o_c1 = out + 98304;
    float* o_c2 = out + 131072;
    float* o_pred = out + 163840;

    k_encdot<<<2048, 256>>>(enc, attnW);
    k_softpack<<<160, 256>>>(input, h0);
    k_attnsum<<<dim3(64, 4, 4), 256>>>(enc);

    // layer 0 gates: xcat(64,2048) @ [w_ih0|w_hh0]^T, split-K x4
    // (attn columns k<1024 reduced from 4 split-S partials in the load path)
    tc_gemm<<<dim3(32, 4), 256>>>(p_xcat, 2048, p_aspart, 1024,
                                  w_ih0, 1536, w_hh0,
                                  b_ih0, b_hh0, p_gpart, 2048, 512);
    k_cell0<<<128, 256>>>(c0, o_h1, o_c1);

    // layer 1 gates: x1(64,1024) @ [w_ih1|w_hh1]^T, split-K x4
    tc_gemm<<<dim3(32, 4), 256>>>(p_x1, 1024, nullptr, 0,
                                  w_ih1, 512, w_hh1,
                                  b_ih1, b_hh1, p_gpart, 2048, 256);
    k_cell1<<<128, 256>>>(c0 + 32768, o_output, o_h2, o_c2);

    // pred: h2(64,512) @ out_W^T + out_b -> (64, 32000)
    tc_gemm<<<dim3(500, 1), 256>>>(p_h2f, 512, nullptr, 0,
                                   out_W, 512, nullptr,
                                   out_b, nullptr, o_pred, 32000, 512);
}

// round 8
// speedup vs baseline: 1.1373x; 1.1373x over previous
#include <cuda_runtime.h>
#include <cuda_bf16.h>
#include <math.h>

#define Bsz 64
#define Hs  512
#define Ss  256
#define Vv  32000
#define SPLITK 8

// ------------------- scratch (__device__ globals, no allocation) -------------
__device__ float g_edt[Bsz * Ss];            // encdot [b'][s']
__device__ float g_norm[Ss * Bsz];           // normalized [s][b]
__device__ float g_aspart[4 * Bsz * 1024];   // attn_sum split-S partials [sp][b][d]
__device__ float g_gpart[SPLITK * Bsz * 2048];  // split-K partial gates
__device__ float g_xcat[Bsz * 2048];         // fp32 [.. | input(1024:1536) | h0[0](1536:2048)]
__device__ float g_x1[Bsz * 1024];           // fp32 [h1(0:512) | h0[1](512:1024)]
__device__ float g_h2f[Bsz * 512];           // fp32 h2

__device__ __forceinline__ void bfsplit(float x, __nv_bfloat16& h, __nv_bfloat16& l) {
    h = __float2bfloat16(x);
    l = __float2bfloat16(x - __bfloat162float(h));
}

// ------------------- attention: encdot[s',b'] = enc[s',b',:] . We ------------
__global__ void k_encdot(const float* __restrict__ enc,
                         const float* __restrict__ attn_W) {
    __shared__ __align__(16) float We[1024];
    for (int i = threadIdx.x; i < 1024; i += blockDim.x) We[i] = attn_W[512 + i];
    __syncthreads();
    int wid  = (blockIdx.x * blockDim.x + threadIdx.x) >> 5;
    int lane = threadIdx.x & 31;
    const float4* e4 = (const float4*)(enc + (size_t)wid * 1024);
    const float4* w4 = (const float4*)We;
    float acc = 0.f;
#pragma unroll
    for (int it = 0; it < 8; it++) {
        float4 a = e4[it * 32 + lane];
        float4 w = w4[it * 32 + lane];
        acc += a.x * w.x + a.y * w.y + a.z * w.z + a.w * w.w;
    }
#pragma unroll
    for (int o = 16; o; o >>= 1) acc += __shfl_xor_sync(0xFFFFFFFFu, acc, o);
    if (lane == 0) {
        int sp = wid >> 6, bp = wid & 63;
        g_edt[bp * 256 + sp] = acc;
    }
}

// ------------------- fused softmax + pack (fp32) -----------------------------
__global__ void k_softpack(const float* __restrict__ input,
                           const float* __restrict__ h0) {
    if (blockIdx.x < 32) {
        int s    = (blockIdx.x * blockDim.x + threadIdx.x) >> 5;
        int lane = threadIdx.x & 31;
        int base = (s >> 2) * 256 + (s & 3) * 64;
        float v0 = g_edt[base + lane];
        float v1 = g_edt[base + 32 + lane];
        float m = fmaxf(v0, v1);
#pragma unroll
        for (int o = 16; o; o >>= 1) m = fmaxf(m, __shfl_xor_sync(0xFFFFFFFFu, m, o));
        float e0 = expf(v0 - m), e1 = expf(v1 - m);
        float sum = e0 + e1;
#pragma unroll
        for (int o = 16; o; o >>= 1) sum += __shfl_xor_sync(0xFFFFFFFFu, sum, o);
        float inv = 1.f / sum;
        g_norm[s * 64 + lane]      = e0 * inv;
        g_norm[s * 64 + 32 + lane] = e1 * inv;
    } else {
        int i = (blockIdx.x - 32) * blockDim.x + threadIdx.x;   // 0..32767
        int b = i >> 9, j = i & 511;
        g_xcat[b * 2048 + 1024 + j] = input[i];
        g_xcat[b * 2048 + 1536 + j] = h0[i];            // h0[0]
        g_x1[b * 1024 + 512 + j]    = h0[32768 + i];    // h0[1]
    }
}

// ------------------- attn_sum split-S partials -------------------------------
__global__ void k_attnsum(const float* __restrict__ enc) {
    int b     = blockIdx.x;        // 0..63
    int chunk = blockIdx.y;        // 0..3
    int sp    = blockIdx.z;        // 0..3 (S split)
    __shared__ float nc[64];
    if (threadIdx.x < 64)
        nc[threadIdx.x] = g_norm[(sp * 64 + threadIdx.x) * 64 + b];
    __syncthreads();
    int d = chunk * 256 + threadIdx.x;
    const float* ep = enc + (size_t)sp * 64 * 65536 + b * 1024 + d;
    float a0 = 0.f, a1 = 0.f, a2 = 0.f, a3 = 0.f;
#pragma unroll 4
    for (int s = 0; s < 64; s += 4) {
        a0 += nc[s]     * ep[(s)     * 65536];
        a1 += nc[s + 1] * ep[(s + 1) * 65536];
        a2 += nc[s + 2] * ep[(s + 2) * 65536];
        a3 += nc[s + 3] * ep[(s + 3) * 65536];
    }
    g_aspart[(sp * 64 + b) * 1024 + d] = (a0 + a1) + (a2 + a3);
}

// ------------------- tensor-core GEMM: out = A(64,K) @ [WA|WB]^T + bias ------
// A fp32; hi/lo bf16 split in the smem-store stage. For k < partK the A row is
// the sum of 4 split-S partials (row stride 1024). Double-buffered smem.
__device__ __forceinline__ void ldmx4(unsigned* r, unsigned addr) {
    asm volatile("ldmatrix.sync.aligned.m8n8.x4.shared.b16 {%0,%1,%2,%3}, [%4];"
                 : "=r"(r[0]), "=r"(r[1]), "=r"(r[2]), "=r"(r[3]) : "r"(addr));
}
__device__ __forceinline__ void mma16816(float* d, const unsigned* a, const unsigned* b) {
    asm volatile("mma.sync.aligned.m16n8k16.row.col.f32.bf16.bf16.f32 "
                 "{%0,%1,%2,%3},{%4,%5,%6,%7},{%8,%9},{%0,%1,%2,%3};"
                 : "+f"(d[0]), "+f"(d[1]), "+f"(d[2]), "+f"(d[3])
                 : "r"(a[0]), "r"(a[1]), "r"(a[2]), "r"(a[3]), "r"(b[0]), "r"(b[1]));
}
// split 8 floats into hi uint4 + lo uint4 in one pass
__device__ __forceinline__ void pack8both(float4 v0, float4 v1, uint4& rh, uint4& rl) {
    float f[8] = {v0.x, v0.y, v0.z, v0.w, v1.x, v1.y, v1.z, v1.w};
    unsigned ph[4], pl[4];
#pragma unroll
    for (int i = 0; i < 4; i++) {
        __nv_bfloat16 h0, l0, h1, l1;
        bfsplit(f[2 * i], h0, l0);
        bfsplit(f[2 * i + 1], h1, l1);
        __nv_bfloat162 H; H.x = h0; H.y = h1;
        __nv_bfloat162 L; L.x = l0; L.y = l1;
        ph[i] = *(unsigned*)&H;
        pl[i] = *(unsigned*)&L;
    }
    rh.x = ph[0]; rh.y = ph[1]; rh.z = ph[2]; rh.w = ph[3];
    rl.x = pl[0]; rl.y = pl[1]; rl.z = pl[2]; rl.w = pl[3];
}

__global__ void __launch_bounds__(256) tc_gemm(
    const float* __restrict__ A, int K,
    const float* __restrict__ Apart, int partK,
    const float* __restrict__ WA, int KA, const float* __restrict__ WB,
    const float* __restrict__ bias0, const float* __restrict__ bias1,
    float* __restrict__ out, int N, int kChunk)
{
    __shared__ __align__(16) __nv_bfloat16 sAh[2][64 * 40], sAl[2][64 * 40];
    __shared__ __align__(16) __nv_bfloat16 sBh[2][64 * 40], sBl[2][64 * 40];
    int tid = threadIdx.x, warp = tid >> 5, lane = tid & 31;
    int warp_m = warp >> 2, warp_n = warp & 3;
    int j0   = blockIdx.x * 64;
    int kidx = blockIdx.y;
    int kbeg = kidx * kChunk, kend = kbeg + kChunk;
    int KB = K - KA;
    float acc[2][2][4] = {};

    // ldmatrix lane->address components (validated mapping)
    int a_row = lane & 15;
    int a_k   = (lane >> 4) * 8;
    int b_row = warp_n * 16 + ((lane >> 4) << 3) + (lane & 7);
    int b_k   = ((lane >> 3) & 1) * 8;

    unsigned sAh_b = (unsigned)__cvta_generic_to_shared(&sAh[0][0]);
    unsigned sAl_b = (unsigned)__cvta_generic_to_shared(&sAl[0][0]);
    unsigned sBh_b = (unsigned)__cvta_generic_to_shared(&sBh[0][0]);
    unsigned sBl_b = (unsigned)__cvta_generic_to_shared(&sBl[0][0]);
    const unsigned STG = 64 * 40 * 2;   // 5120 bytes per stage

    int arow = tid >> 2, ac8 = tid & 3;            // A: 64 rows x 4 groups of 8 cols
    int wrow = tid >> 3, wc4 = tid & 7;            // W: 32 rows x 8 float4 (x2 halves)

    float4 rA0, rA1, rW0, rW1;

    auto loadregs = [&](int k0) {
        if (k0 < partK) {
            const float* p0 = Apart + (size_t)arow * 1024 + k0 + ac8 * 8;
            rA0 = *(const float4*)p0;
            rA1 = *(const float4*)(p0 + 4);
#pragma unroll
            for (int p = 1; p < 4; p++) {
                float4 u0 = *(const float4*)(p0 + p * 65536);
                float4 u1 = *(const float4*)(p0 + p * 65536 + 4);
                rA0.x += u0.x; rA0.y += u0.y; rA0.z += u0.z; rA0.w += u0.w;
                rA1.x += u1.x; rA1.y += u1.y; rA1.z += u1.z; rA1.w += u1.w;
            }
        } else {
            const float* pa = A + (size_t)arow * K + k0 + ac8 * 8;
            rA0 = *(const float4*)pa;
            rA1 = *(const float4*)(pa + 4);
        }
        const float* wp; int ld, kc;
        if (k0 < KA) { wp = WA; ld = KA; kc = k0; }
        else         { wp = WB; ld = KB; kc = k0 - KA; }
        rW0 = *(const float4*)(wp + (size_t)(j0 + wrow) * ld + kc + wc4 * 4);
        rW1 = *(const float4*)(wp + (size_t)(j0 + wrow + 32) * ld + kc + wc4 * 4);
    };
    auto storeregs = [&](int st) {
        uint4 rh, rl;
        pack8both(rA0, rA1, rh, rl);
        *(uint4*)((char*)sAh[st] + arow * 80 + ac8 * 16) = rh;
        *(uint4*)((char*)sAl[st] + arow * 80 + ac8 * 16) = rl;
#pragma unroll
        for (int half = 0; half < 2; half++) {
            float4 v = half ? rW1 : rW0;
            int row = wrow + half * 32;
            __nv_bfloat16 hx, lx, hy, ly, hz, lz, hw, lw;
            bfsplit(v.x, hx, lx); bfsplit(v.y, hy, ly);
            bfsplit(v.z, hz, lz); bfsplit(v.w, hw, lw);
            __nv_bfloat162 H0; H0.x = hx; H0.y = hy;
            __nv_bfloat162 H1; H1.x = hz; H1.y = hw;
            __nv_bfloat162 L0; L0.x = lx; L0.y = ly;
            __nv_bfloat162 L1; L1.x = lz; L1.y = lw;
            char* bh = (char*)sBh[st] + row * 80 + wc4 * 8;
            char* bl = (char*)sBl[st] + row * 80 + wc4 * 8;
            *(__nv_bfloat162*)bh = H0; *(__nv_bfloat162*)(bh + 4) = H1;
            *(__nv_bfloat162*)bl = L0; *(__nv_bfloat162*)(bl + 4) = L1;
        }
    };

    int nIter = (kend - kbeg) >> 5;
    loadregs(kbeg);
    storeregs(0);
    __syncthreads();
    int stage = 0;
    for (int it = 0; it < nIter; it++) {
        bool has_next = (it + 1 < nIter);
        if (has_next) loadregs(kbeg + (it + 1) * 32);
        unsigned sb = stage * STG;
#pragma unroll
        for (int kk = 0; kk < 32; kk += 16) {
            unsigned bh[4], bl[4];
            unsigned baddr = (unsigned)(b_row * 80 + (kk + b_k) * 2) + sb;
            ldmx4(bh, sBh_b + baddr);
            ldmx4(bl, sBl_b + baddr);
#pragma unroll
            for (int mi = 0; mi < 2; mi++) {
                unsigned ah[4], al[4];
                int grow = warp_m * 32 + mi * 16 + a_row;
                unsigned aaddr = (unsigned)(grow * 80 + (kk + a_k) * 2) + sb;
                ldmx4(ah, sAh_b + aaddr);
                ldmx4(al, sAl_b + aaddr);
                mma16816(acc[mi][0], ah, &bh[0]);
                mma16816(acc[mi][0], ah, &bl[0]);
                mma16816(acc[mi][0], al, &bh[0]);
                mma16816(acc[mi][1], ah, &bh[2]);
                mma16816(acc[mi][1], ah, &bl[2]);
                mma16816(acc[mi][1], al, &bh[2]);
            }
        }
        if (has_next) storeregs(stage ^ 1);
        __syncthreads();
        stage ^= 1;
    }

    int orow = lane >> 2;
    int ocol = (lane & 3) * 2;
    float* op = out + (size_t)kidx * 64 * N;
#pragma unroll
    for (int mi = 0; mi < 2; mi++) {
#pragma unroll
        for (int nj = 0; nj < 2; nj++) {
            int col = j0 + warp_n * 16 + nj * 8 + ocol;
            float bA = 0.f, bB = 0.f;
            if (kidx == 0) {
                if (bias0) { bA += bias0[col]; bB += bias0[col + 1]; }
                if (bias1) { bA += bias1[col]; bB += bias1[col + 1]; }
            }
            int r0 = warp_m * 32 + mi * 16 + orow;
            op[(size_t)r0 * N + col]           = acc[mi][nj][0] + bA;
            op[(size_t)r0 * N + col + 1]       = acc[mi][nj][1] + bB;
            op[(size_t)(r0 + 8) * N + col]     = acc[mi][nj][2] + bA;
            op[(size_t)(r0 + 8) * N + col + 1] = acc[mi][nj][3] + bB;
        }
    }
}

// ------------------- LSTM cell epilogues (sum split-K parts) -----------------
__device__ __forceinline__ float sigf(float x) { return 1.f / (1.f + expf(-x)); }

__global__ void k_cell0(const float* __restrict__ c0,
                        float* __restrict__ h_out,
                        float* __restrict__ c_out) {
    int idx = blockIdx.x * blockDim.x + threadIdx.x;
    int b = idx >> 9, j = idx & 511;
    int base = b * 2048;
    float gi = 0, gf = 0, gg = 0, go = 0;
#pragma unroll
    for (int p = 0; p < SPLITK; p++) {
        const float* gp = g_gpart + p * 64 * 2048 + base;
        gi += gp[j]; gf += gp[512 + j]; gg += gp[1024 + j]; go += gp[1536 + j];
    }
    float c = sigf(gf) * c0[idx] + sigf(gi) * tanhf(gg);
    float h = sigf(go) * tanhf(c);
    h_out[idx] = h;
    c_out[idx] = c;
    g_x1[b * 1024 + j] = h;
}

__global__ void k_cell1(const float* __restrict__ c0b,
                        float* __restrict__ out0,
                        float* __restrict__ h_out,
                        float* __restrict__ c_out) {
    int idx = blockIdx.x * blockDim.x + threadIdx.x;
    int b = idx >> 9, j = idx & 511;
    int base = b * 2048;
    float gi = 0, gf = 0, gg = 0, go = 0;
#pragma unroll
    for (int p = 0; p < SPLITK; p++) {
        const float* gp = g_gpart + p * 64 * 2048 + base;
        gi += gp[j]; gf += gp[512 + j]; gg += gp[1024 + j]; go += gp[1536 + j];
    }
    float c = sigf(gf) * c0b[idx] + sigf(gi) * tanhf(gg);
    float h = sigf(go) * tanhf(c);
    out0[idx]  = h;
    h_out[idx] = h;
    c_out[idx] = c;
    g_h2f[idx] = h;
}

// ------------------- launch ---------------------------------------------------
extern "C" void kernel_launch(void* const* d_in, const int* in_sizes, int n_in,
                              void* d_out, int out_size) {
    const float* input = (const float*)d_in[0];
    const float* h0    = (const float*)d_in[1];
    const float* c0    = (const float*)d_in[2];
    const float* enc   = (const float*)d_in[3];
    const float* attnW = (const float*)d_in[4];
    const float* w_ih0 = (const float*)d_in[6];
    const float* w_hh0 = (const float*)d_in[7];
    const float* b_ih0 = (const float*)d_in[8];
    const float* b_hh0 = (const float*)d_in[9];
    const float* w_ih1 = (const float*)d_in[10];
    const float* w_hh1 = (const float*)d_in[11];
    const float* b_ih1 = (const float*)d_in[12];
    const float* b_hh1 = (const float*)d_in[13];
    const float* out_W = (const float*)d_in[14];
    const float* out_b = (const float*)d_in[15];
    float* out = (float*)d_out;

    float *p_gpart, *p_xcat, *p_x1, *p_h2f, *p_aspart;
    cudaGetSymbolAddress((void**)&p_gpart,  g_gpart);
    cudaGetSymbolAddress((void**)&p_xcat,   g_xcat);
    cudaGetSymbolAddress((void**)&p_x1,     g_x1);
    cudaGetSymbolAddress((void**)&p_h2f,    g_h2f);
    cudaGetSymbolAddress((void**)&p_aspart, g_aspart);

    // Output layout: [output | h_new | c_new | pred]
    float* o_output = out;
    float* o_h1 = out + 32768;
    float* o_h2 = out + 65536;
    float* o_c1 = out + 98304;
    float* o_c2 = out + 131072;
    float* o_pred = out + 163840;

    k_encdot<<<2048, 256>>>(enc, attnW);
    k_softpack<<<160, 256>>>(input, h0);
    k_attnsum<<<dim3(64, 4, 4), 256>>>(enc);

    // layer 0 gates: xcat(64,2048) @ [w_ih0|w_hh0]^T, split-K x8 (kChunk 256)
    tc_gemm<<<dim3(32, SPLITK), 256>>>(p_xcat, 2048, p_aspart, 1024,
                                       w_ih0, 1536, w_hh0,
                                       b_ih0, b_hh0, p_gpart, 2048, 256);
    k_cell0<<<128, 256>>>(c0, o_h1, o_c1);

    // layer 1 gates: x1(64,1024) @ [w_ih1|w_hh1]^T, split-K x8 (kChunk 128)
    tc_gemm<<<dim3(32, SPLITK), 256>>>(p_x1, 1024, nullptr, 0,
                                       w_ih1, 512, w_hh1,
                                       b_ih1, b_hh1, p_gpart, 2048, 128);
    k_cell1<<<128, 256>>>(c0 + 32768, o_output, o_h2, o_c2);

    // pred: h2(64,512) @ out_W^T + out_b -> (64, 32000)
    tc_gemm<<<dim3(500, 1), 256>>>(p_h2f, 512, nullptr, 0,
                                   out_W, 512, nullptr,
                                   out_b, nullptr, o_pred, 32000, 512);
}